// round 10
// baseline (speedup 1.0000x reference)
#include <cuda_runtime.h>
#include <cuda_fp16.h>
#include <math.h>

#define NN 100000
#define NE 1200000
#define DH 64
#define NG 128
#define SCAN_CHUNK 1024
#define NCHUNK 98            // ceil(NN / SCAN_CHUNK)

// gemm smem: sWr(4096) + sWs(4096) + sAt(64*132) + sXt(64*132) floats
#define GEMM_SMEM ((4096 + 4096 + 8448 + 8448) * 4)   // 100352 B -> 2 blocks/SM

// packed f32x2 FMA: d.lo += a.lo*b.lo ; d.hi += a.hi*b.hi  (PTX-only pattern)
#define FMA2(d, a, b) asm("fma.rn.f32x2 %0, %1, %2, %0;" : "+l"(d) : "l"(a), "l"(b))
#define UNPK(lo, hi, in) asm("mov.b64 {%0, %1}, %2;" : "=f"(lo), "=f"(hi) : "l"(in))
#define PACK2(d, s) asm("mov.b64 %0, {%1, %1};" : "=l"(d) : "f"(s))

// -------- scratch (static device allocations; no cudaMalloc anywhere) --------
__device__ int                g_deg[NN];
__device__ unsigned long long g_scanpkt[NCHUNK];   // (flag<<32)|value; 1=agg, 2=prefix
__device__ int                g_rowptr[NN + 1];
__device__ int                g_cursor[NN];
__device__ int                g_esrc[NE];
__device__ float              g_agg[(size_t)NN * DH];
__device__ float              g_hA[(size_t)NN * DH];
__device__ float              g_hB[(size_t)NN * DH];
__device__ uint2              g_xh[(size_t)NN * 16];   // fp16 shadow of x   (64 halves/row)
__device__ uint2              g_hAh[(size_t)NN * 16];  // fp16 shadow of hA
__device__ uint2              g_hBh[(size_t)NN * 16];  // fp16 shadow of hB
__device__ float              g_pool[NG * DH];

// ---------------- CSR build: counting sort of edges by dst ----------------
__global__ void k_hist(const int* __restrict__ dst) {
    int e = blockIdx.x * blockDim.x + threadIdx.x;
    if (e < NE) atomicAdd(&g_deg[dst[e]], 1);
}

// One-kernel exclusive scan of g_deg -> g_rowptr via decoupled lookback.
__global__ void k_scan() {
    __shared__ int s[SCAN_CHUNK];
    __shared__ int s_excl;
    int b = blockIdx.x, t = threadIdx.x;
    int idx = b * SCAN_CHUNK + t;
    int d = (idx < NN) ? g_deg[idx] : 0;
    s[t] = d;
    __syncthreads();
    for (int off = 1; off < SCAN_CHUNK; off <<= 1) {
        int v = (t >= off) ? s[t - off] : 0;
        __syncthreads();
        s[t] += v;
        __syncthreads();
    }
    int total = s[SCAN_CHUNK - 1];

    if (t == 0) {
        int excl = 0;
        if (b == 0) {
            atomicExch(&g_scanpkt[0], (2ull << 32) | (unsigned)total);
        } else {
            atomicExch(&g_scanpkt[b], (1ull << 32) | (unsigned)total);
            int run = 0;
            for (int p = b - 1; p >= 0; p--) {
                unsigned long long v;
                do { v = atomicAdd(&g_scanpkt[p], 0ull); } while ((v >> 32) == 0ull);
                run += (int)(v & 0xffffffffull);
                if ((v >> 32) == 2ull) break;
            }
            excl = run;
            atomicExch(&g_scanpkt[b], (2ull << 32) | (unsigned)(excl + total));
        }
        s_excl = excl;
        if (b == NCHUNK - 1) g_rowptr[NN] = excl + total;   // == NE
    }
    __syncthreads();
    int excl = s_excl;
    if (idx < NN) {
        int e = s[t] - d + excl;
        g_rowptr[idx] = e;
        g_cursor[idx] = e;
    }
}

__global__ void k_scatter(const int* __restrict__ src, const int* __restrict__ dst) {
    int e = blockIdx.x * blockDim.x + threadIdx.x;
    if (e < NE) {
        int p = atomicAdd(&g_cursor[dst[e]], 1);
        g_esrc[p] = src[e];
    }
}

// ---------------- fp32 -> fp16 shadow convert (x only; layers write their own) ----
__global__ void k_cvt(const float* __restrict__ in, uint2* __restrict__ outh) {
    int i = blockIdx.x * blockDim.x + threadIdx.x;    // one uint2 (4 halves) each
    if (i >= NN * 16) return;
    float4 f = *(const float4*)(in + (size_t)i * 4);
    __half2 h0 = __floats2half2_rn(f.x, f.y);
    __half2 h1 = __floats2half2_rn(f.z, f.w);
    uint2 u;
    u.x = *(unsigned*)&h0;
    u.y = *(unsigned*)&h1;
    outh[i] = u;
}

// ---------------- neighbor aggregation (fp16 gather, fp32 accumulate) ----------------
// 16 threads per node, one uint2 (4 halves) each; 4-wide index batching for MLP>=4.
// 128 B/edge instead of 256 B -> half the L2 traffic of the fp32 gather.
__device__ __forceinline__ void acc4(float* a, uint2 v) {
    __half2 h0 = *reinterpret_cast<__half2*>(&v.x);
    __half2 h1 = *reinterpret_cast<__half2*>(&v.y);
    float2 f0 = __half22float2(h0);
    float2 f1 = __half22float2(h1);
    a[0] += f0.x; a[1] += f0.y; a[2] += f1.x; a[3] += f1.y;
}

__global__ void k_agg(const uint2* __restrict__ inh) {
    int t = threadIdx.x;
    int n = blockIdx.x * 16 + (t >> 4);
    int c = (t & 15);                 // uint2 index within row (16 per row)
    if (n >= NN) return;
    int rb = g_rowptr[n], re = g_rowptr[n + 1];
    float a0[4] = {0.f, 0.f, 0.f, 0.f};
    float a1[4] = {0.f, 0.f, 0.f, 0.f};
    int j = rb;
    for (; j + 4 <= re; j += 4) {
        int s0 = g_esrc[j],     s1 = g_esrc[j + 1];
        int s2 = g_esrc[j + 2], s3 = g_esrc[j + 3];
        uint2 v0 = inh[(size_t)s0 * 16 + c];
        uint2 v1 = inh[(size_t)s1 * 16 + c];
        uint2 v2 = inh[(size_t)s2 * 16 + c];
        uint2 v3 = inh[(size_t)s3 * 16 + c];
        acc4(a0, v0); acc4(a1, v1); acc4(a0, v2); acc4(a1, v3);
    }
    for (; j < re; j++) {
        uint2 v0 = inh[(size_t)g_esrc[j] * 16 + c];
        acc4(a0, v0);
    }
    float4 o;
    o.x = a0[0] + a1[0]; o.y = a0[1] + a1[1];
    o.z = a0[2] + a1[2]; o.w = a0[3] + a1[3];
    *(float4*)(g_agg + (size_t)n * 64 + c * 4) = o;
}

// k-dependent XOR swizzle of the row dimension (16B-block granularity)
__device__ __forceinline__ int swz(int k, int r) {
    return k * 132 + (((((r) >> 2) ^ (k & 7)) << 2) | (r & 3));
}

// ------------- transform: out = relu(agg@Wr + x@Ws + br); also writes fp16 shadow ----
__global__ void __launch_bounds__(256, 2)
k_gemm(const float* __restrict__ Aagg, const float* __restrict__ Ax,
       const float* __restrict__ Wr,   const float* __restrict__ Ws,
       const float* __restrict__ br,   float* __restrict__ out,
       __half* __restrict__ outh) {
    extern __shared__ float sm[];
    float* sWr = sm;                  // [64 k][64 c]
    float* sWs = sm + 4096;           // [64 k][64 c]
    float* sAt = sm + 8192;           // [64 k][132] swizzled-transposed agg
    float* sXt = sm + 8192 + 8448;    // [64 k][132] swizzled-transposed x
    int t = threadIdx.x;
    int n0g = blockIdx.x * 128;

    for (int idx = t; idx < 1024; idx += 256) {
        float4 wr = *(const float4*)(Wr + idx * 4);
        float4 ws = *(const float4*)(Ws + idx * 4);
        *(float4*)(sWr + idx * 4) = wr;
        *(float4*)(sWs + idx * 4) = ws;
    }
    for (int idx = t; idx < 2048; idx += 256) {   // 128 rows x 16 float4
        int r = idx >> 4, k4 = (idx & 15) * 4;
        int n = n0g + r;
        float4 va = make_float4(0.f, 0.f, 0.f, 0.f);
        float4 vx = va;
        if (n < NN) {
            va = *(const float4*)(Aagg + (size_t)n * 64 + k4);
            vx = *(const float4*)(Ax   + (size_t)n * 64 + k4);
        }
        sAt[swz(k4 + 0, r)] = va.x; sAt[swz(k4 + 1, r)] = va.y;
        sAt[swz(k4 + 2, r)] = va.z; sAt[swz(k4 + 3, r)] = va.w;
        sXt[swz(k4 + 0, r)] = vx.x; sXt[swz(k4 + 1, r)] = vx.y;
        sXt[swz(k4 + 2, r)] = vx.z; sXt[swz(k4 + 3, r)] = vx.w;
    }
    __syncthreads();

    int q  = t & 15;          // owns cols {2q, 2q+1, 32+2q, 32+2q+1}
    int n0 = (t >> 4) * 8;    // 8 consecutive rows

    unsigned long long acc[16];
#pragma unroll
    for (int i = 0; i < 16; i++) acc[i] = 0ull;

#pragma unroll 8
    for (int k = 0; k < 64; k++) {
        float2 wrA = *(const float2*)(sWr + k * 64 + 2 * q);
        float2 wrB = *(const float2*)(sWr + k * 64 + 32 + 2 * q);
        float2 wsA = *(const float2*)(sWs + k * 64 + 2 * q);
        float2 wsB = *(const float2*)(sWs + k * 64 + 32 + 2 * q);
        unsigned long long wrA0, wrA1, wrB0, wrB1, wsA0, wsA1, wsB0, wsB1;
        PACK2(wrA0, wrA.x); PACK2(wrA1, wrA.y);
        PACK2(wrB0, wrB.x); PACK2(wrB1, wrB.y);
        PACK2(wsA0, wsA.x); PACK2(wsA1, wsA.y);
        PACK2(wsB0, wsB.x); PACK2(wsB1, wsB.y);

        int offA = k * 132 + ((((n0 >> 2) + 0) ^ (k & 7)) << 2);  // rows n0..n0+3
        int offB = k * 132 + ((((n0 >> 2) + 1) ^ (k & 7)) << 2);  // rows n0+4..n0+7
        ulonglong2 a01 = *(const ulonglong2*)(sAt + offA);
        ulonglong2 a23 = *(const ulonglong2*)(sAt + offB);
        ulonglong2 x01 = *(const ulonglong2*)(sXt + offA);
        ulonglong2 x23 = *(const ulonglong2*)(sXt + offB);

        FMA2(acc[0],  a01.x, wrA0); FMA2(acc[0],  x01.x, wsA0);
        FMA2(acc[1],  a01.x, wrA1); FMA2(acc[1],  x01.x, wsA1);
        FMA2(acc[2],  a01.x, wrB0); FMA2(acc[2],  x01.x, wsB0);
        FMA2(acc[3],  a01.x, wrB1); FMA2(acc[3],  x01.x, wsB1);

        FMA2(acc[4],  a01.y, wrA0); FMA2(acc[4],  x01.y, wsA0);
        FMA2(acc[5],  a01.y, wrA1); FMA2(acc[5],  x01.y, wsA1);
        FMA2(acc[6],  a01.y, wrB0); FMA2(acc[6],  x01.y, wsB0);
        FMA2(acc[7],  a01.y, wrB1); FMA2(acc[7],  x01.y, wsB1);

        FMA2(acc[8],  a23.x, wrA0); FMA2(acc[8],  x23.x, wsA0);
        FMA2(acc[9],  a23.x, wrA1); FMA2(acc[9],  x23.x, wsA1);
        FMA2(acc[10], a23.x, wrB0); FMA2(acc[10], x23.x, wsB0);
        FMA2(acc[11], a23.x, wrB1); FMA2(acc[11], x23.x, wsB1);

        FMA2(acc[12], a23.y, wrA0); FMA2(acc[12], x23.y, wsA0);
        FMA2(acc[13], a23.y, wrA1); FMA2(acc[13], x23.y, wsA1);
        FMA2(acc[14], a23.y, wrB0); FMA2(acc[14], x23.y, wsB0);
        FMA2(acc[15], a23.y, wrB1); FMA2(acc[15], x23.y, wsB1);
    }

    int cA = 2 * q;
    int cB = 32 + 2 * q;
    float bA0 = br[cA], bA1 = br[cA + 1], bB0 = br[cB], bB1 = br[cB + 1];

#pragma unroll
    for (int rp = 0; rp < 4; rp++) {
        float vA0lo, vA0hi, vA1lo, vA1hi, vB0lo, vB0hi, vB1lo, vB1hi;
        UNPK(vA0lo, vA0hi, acc[rp * 4 + 0]);
        UNPK(vA1lo, vA1hi, acc[rp * 4 + 1]);
        UNPK(vB0lo, vB0hi, acc[rp * 4 + 2]);
        UNPK(vB1lo, vB1hi, acc[rp * 4 + 3]);
        int rlo = n0g + n0 + 2 * rp;
        if (rlo < NN) {
            float2 oA = make_float2(fmaxf(vA0lo + bA0, 0.f), fmaxf(vA1lo + bA1, 0.f));
            float2 oB = make_float2(fmaxf(vB0lo + bB0, 0.f), fmaxf(vB1lo + bB1, 0.f));
            *(float2*)(out + (size_t)rlo * 64 + cA) = oA;
            *(float2*)(out + (size_t)rlo * 64 + cB) = oB;
            __half2 hA2 = __floats2half2_rn(oA.x, oA.y);
            __half2 hB2 = __floats2half2_rn(oB.x, oB.y);
            *(__half2*)(outh + (size_t)rlo * 64 + cA) = hA2;
            *(__half2*)(outh + (size_t)rlo * 64 + cB) = hB2;
        }
        if (rlo + 1 < NN) {
            float2 oA = make_float2(fmaxf(vA0hi + bA0, 0.f), fmaxf(vA1hi + bA1, 0.f));
            float2 oB = make_float2(fmaxf(vB0hi + bB0, 0.f), fmaxf(vB1hi + bB1, 0.f));
            *(float2*)(out + (size_t)(rlo + 1) * 64 + cA) = oA;
            *(float2*)(out + (size_t)(rlo + 1) * 64 + cB) = oB;
            __half2 hA2 = __floats2half2_rn(oA.x, oA.y);
            __half2 hB2 = __floats2half2_rn(oB.x, oB.y);
            *(__half2*)(outh + (size_t)(rlo + 1) * 64 + cA) = hA2;
            *(__half2*)(outh + (size_t)(rlo + 1) * 64 + cB) = hB2;
        }
    }
}

// ---------------- global add pool (batch is sorted -> ranges) ----------------
__device__ __forceinline__ int lower_bound_i(const int* __restrict__ a, int n, int v) {
    int lo = 0, hi = n;
    while (lo < hi) {
        int mid = (lo + hi) >> 1;
        if (a[mid] < v) lo = mid + 1; else hi = mid;
    }
    return lo;
}

__global__ void k_pool(const float* __restrict__ h, const int* __restrict__ batch) {
    __shared__ float red[512];
    int g = blockIdx.x, t = threadIdx.x;
    int c = t & 63, q = t >> 6;
    int start = lower_bound_i(batch, NN, g);
    int end   = lower_bound_i(batch, NN, g + 1);
    float acc = 0.f;
    for (int n = start + q; n < end; n += 8) acc += h[(size_t)n * 64 + c];
    red[t] = acc;
    __syncthreads();
    if (q < 4) red[t] += red[t + 256];
    __syncthreads();
    if (q < 2) red[t] += red[t + 128];
    __syncthreads();
    if (q == 0)
        g_pool[g * 64 + c] = red[c] + red[c + 64];
}

// ---------------- FC head + log_softmax ----------------
__global__ void k_fc(const float* __restrict__ W1, const float* __restrict__ b1,
                     const float* __restrict__ W2, const float* __restrict__ b2,
                     float* __restrict__ out) {
    __shared__ float sg[64], sh[64], sl[3];
    int g = blockIdx.x, t = threadIdx.x;
    sg[t] = g_pool[g * 64 + t];
    __syncthreads();
    float a = b1[t];
#pragma unroll 8
    for (int k = 0; k < 64; k++) a += sg[k] * W1[k * 64 + t];
    sh[t] = fmaxf(a, 0.f);
    __syncthreads();
    if (t < 3) {
        float l = b2[t];
        for (int k = 0; k < 64; k++) l += sh[k] * W2[k * 3 + t];
        sl[t] = l;
    }
    __syncthreads();
    if (t < 3) {
        float m = fmaxf(sl[0], fmaxf(sl[1], sl[2]));
        float s = expf(sl[0] - m) + expf(sl[1] - m) + expf(sl[2] - m);
        out[g * 3 + t] = sl[t] - m - logf(s);
    }
}

// ------------------------------- launcher -------------------------------
extern "C" void kernel_launch(void* const* d_in, const int* in_sizes, int n_in,
                              void* d_out, int out_size) {
    const float* x     = (const float*)d_in[0];
    const int*   ei    = (const int*)d_in[1];
    const int*   src   = ei;
    const int*   dst   = ei + NE;
    const int*   batch = (const int*)d_in[2];
    const float* Wr1 = (const float*)d_in[3];
    const float* br1 = (const float*)d_in[4];
    const float* Ws1 = (const float*)d_in[5];
    const float* Wr2 = (const float*)d_in[6];
    const float* br2 = (const float*)d_in[7];
    const float* Ws2 = (const float*)d_in[8];
    const float* Wr3 = (const float*)d_in[9];
    const float* br3 = (const float*)d_in[10];
    const float* Ws3 = (const float*)d_in[11];
    const float* Wf1 = (const float*)d_in[12];
    const float* bf1 = (const float*)d_in[13];
    const float* Wf2 = (const float*)d_in[14];
    const float* bf2 = (const float*)d_in[15];
    float* out = (float*)d_out;

    cudaFuncSetAttribute(k_gemm, cudaFuncAttributeMaxDynamicSharedMemorySize, GEMM_SMEM);

    float *agg, *hA, *hB;
    uint2 *xh, *hAh, *hBh;
    int* degp;
    unsigned long long* pktp;
    cudaGetSymbolAddress((void**)&agg,  g_agg);
    cudaGetSymbolAddress((void**)&hA,   g_hA);
    cudaGetSymbolAddress((void**)&hB,   g_hB);
    cudaGetSymbolAddress((void**)&xh,   g_xh);
    cudaGetSymbolAddress((void**)&hAh,  g_hAh);
    cudaGetSymbolAddress((void**)&hBh,  g_hBh);
    cudaGetSymbolAddress((void**)&degp, g_deg);
    cudaGetSymbolAddress((void**)&pktp, g_scanpkt);

    // CSR build (counting sort by dst)
    cudaMemsetAsync(degp, 0, NN * sizeof(int));
    cudaMemsetAsync(pktp, 0, NCHUNK * sizeof(unsigned long long));
    k_hist<<<(NE + 255) / 256, 256>>>(dst);
    k_scan<<<NCHUNK, SCAN_CHUNK>>>();
    k_scatter<<<(NE + 255) / 256, 256>>>(src, dst);
    k_cvt<<<(NN * 16 + 255) / 256, 256>>>(x, xh);   // kernel #4 -> gemm L1 is #6 for ncu

    const int AGG_GRID  = (NN + 15) / 16;
    const int GEMM_GRID = (NN + 127) / 128;

    // layer 1
    k_agg<<<AGG_GRID, 256>>>(xh);
    k_gemm<<<GEMM_GRID, 256, GEMM_SMEM>>>(agg, x, Wr1, Ws1, br1, hA, (__half*)hAh);
    // layer 2
    k_agg<<<AGG_GRID, 256>>>(hAh);
    k_gemm<<<GEMM_GRID, 256, GEMM_SMEM>>>(agg, hA, Wr2, Ws2, br2, hB, (__half*)hBh);
    // layer 3
    k_agg<<<AGG_GRID, 256>>>(hBh);
    k_gemm<<<GEMM_GRID, 256, GEMM_SMEM>>>(agg, hB, Wr3, Ws3, br3, hA, (__half*)hAh);

    // pool + head
    k_pool<<<NG, 512>>>(hA, batch);
    k_fc<<<NG, 64>>>(Wf1, bf1, Wf2, bf2, out);
}

// round 13
// speedup vs baseline: 1.1905x; 1.1905x over previous
#include <cuda_runtime.h>
#include <cuda_fp16.h>
#include <math.h>
#include <stdint.h>

#define NN 100000
#define NE 1200000
#define DH 64
#define NG 128
#define SCAN_CHUNK 1024
#define NCHUNK 98            // ceil(NN / SCAN_CHUNK)

// mma gemm smem: sA[128][136] fp16 + sB[64][136] fp16 + bias[64] f32
#define SA_BYTES (128 * 136 * 2)          // 34816
#define SB_BYTES (64 * 136 * 2)           // 17408
#define GEMM_SMEM (SA_BYTES + SB_BYTES + 256)   // 52480 -> 2+ blocks/SM

__device__ __forceinline__ uint32_t s2u(const void* p) {
    uint32_t a;
    asm("{ .reg .u64 t; cvta.to.shared.u64 t, %1; cvt.u32.u64 %0, t; }" : "=r"(a) : "l"(p));
    return a;
}

// -------- scratch (static device allocations; no cudaMalloc anywhere) --------
__device__ int                g_deg[NN];
__device__ unsigned long long g_scanpkt[NCHUNK];
__device__ int                g_rowptr[NN + 1];
__device__ int                g_cursor[NN];
__device__ int                g_esrc[NE];
__device__ uint2              g_xh [(size_t)NN * 16];   // fp16 x      (64 halves/row)
__device__ uint2              g_aggh[(size_t)NN * 16];  // fp16 agg
__device__ uint2              g_hAh[(size_t)NN * 16];   // fp16 layer out A
__device__ uint2              g_hBh[(size_t)NN * 16];   // fp16 layer out B
__device__ float              g_pool[NG * DH];

// ---------- cvt: x fp32 -> fp16; also zero deg + scanpkt (replaces memsets) ----------
__global__ void k_cvt(const float* __restrict__ in, uint2* __restrict__ outh) {
    int i = blockIdx.x * blockDim.x + threadIdx.x;
    if (i < NCHUNK) g_scanpkt[i] = 0ull;
    if (i < NN) g_deg[i] = 0;
    if (i >= NN * 16) return;
    float4 f = *(const float4*)(in + (size_t)i * 4);
    __half2 h0 = __floats2half2_rn(f.x, f.y);
    __half2 h1 = __floats2half2_rn(f.z, f.w);
    uint2 u;
    u.x = *(unsigned*)&h0;
    u.y = *(unsigned*)&h1;
    outh[i] = u;
}

// ---------------- CSR build ----------------
__global__ void k_hist(const int* __restrict__ dst) {
    int e = blockIdx.x * blockDim.x + threadIdx.x;
    if (e < NE) atomicAdd(&g_deg[dst[e]], 1);
}

__global__ void k_scan() {
    __shared__ int s[SCAN_CHUNK];
    __shared__ int s_excl;
    int b = blockIdx.x, t = threadIdx.x;
    int idx = b * SCAN_CHUNK + t;
    int d = (idx < NN) ? g_deg[idx] : 0;
    s[t] = d;
    __syncthreads();
    for (int off = 1; off < SCAN_CHUNK; off <<= 1) {
        int v = (t >= off) ? s[t - off] : 0;
        __syncthreads();
        s[t] += v;
        __syncthreads();
    }
    int total = s[SCAN_CHUNK - 1];
    if (t == 0) {
        int excl = 0;
        if (b == 0) {
            atomicExch(&g_scanpkt[0], (2ull << 32) | (unsigned)total);
        } else {
            atomicExch(&g_scanpkt[b], (1ull << 32) | (unsigned)total);
            int run = 0;
            for (int p = b - 1; p >= 0; p--) {
                unsigned long long v;
                do { v = atomicAdd(&g_scanpkt[p], 0ull); } while ((v >> 32) == 0ull);
                run += (int)(v & 0xffffffffull);
                if ((v >> 32) == 2ull) break;
            }
            excl = run;
            atomicExch(&g_scanpkt[b], (2ull << 32) | (unsigned)(excl + total));
        }
        s_excl = excl;
        if (b == NCHUNK - 1) g_rowptr[NN] = excl + total;
    }
    __syncthreads();
    int excl = s_excl;
    if (idx < NN) {
        int e = s[t] - d + excl;
        g_rowptr[idx] = e;
        g_cursor[idx] = e;
    }
}

__global__ void k_scatter(const int* __restrict__ src, const int* __restrict__ dst) {
    int e = blockIdx.x * blockDim.x + threadIdx.x;
    if (e < NE) {
        int p = atomicAdd(&g_cursor[dst[e]], 1);
        g_esrc[p] = src[e];
    }
}

// ---------------- neighbor aggregation (fp16 gather, fp32 accumulate, fp16 out) ----
__device__ __forceinline__ void acc4(float* a, uint2 v) {
    __half2 h0 = *reinterpret_cast<__half2*>(&v.x);
    __half2 h1 = *reinterpret_cast<__half2*>(&v.y);
    float2 f0 = __half22float2(h0);
    float2 f1 = __half22float2(h1);
    a[0] += f0.x; a[1] += f0.y; a[2] += f1.x; a[3] += f1.y;
}

__global__ void k_agg(const uint2* __restrict__ inh) {
    int t = threadIdx.x;
    int n = blockIdx.x * 16 + (t >> 4);
    int c = (t & 15);
    if (n >= NN) return;
    int rb = g_rowptr[n], re = g_rowptr[n + 1];
    float a0[4] = {0.f, 0.f, 0.f, 0.f};
    float a1[4] = {0.f, 0.f, 0.f, 0.f};
    int j = rb;
    for (; j + 4 <= re; j += 4) {
        int s0 = g_esrc[j],     s1 = g_esrc[j + 1];
        int s2 = g_esrc[j + 2], s3 = g_esrc[j + 3];
        uint2 v0 = inh[(size_t)s0 * 16 + c];
        uint2 v1 = inh[(size_t)s1 * 16 + c];
        uint2 v2 = inh[(size_t)s2 * 16 + c];
        uint2 v3 = inh[(size_t)s3 * 16 + c];
        acc4(a0, v0); acc4(a1, v1); acc4(a0, v2); acc4(a1, v3);
    }
    for (; j < re; j++) {
        uint2 v0 = inh[(size_t)g_esrc[j] * 16 + c];
        acc4(a0, v0);
    }
    __half2 o0 = __floats2half2_rn(a0[0] + a1[0], a0[1] + a1[1]);
    __half2 o1 = __floats2half2_rn(a0[2] + a1[2], a0[3] + a1[3]);
    uint2 u;
    u.x = *(unsigned*)&o0;
    u.y = *(unsigned*)&o1;
    g_aggh[(size_t)n * 16 + c] = u;
}

// ---------- tensor-core transform: out = relu([agg|x] @ [Wr;Ws] + br), fp16 out ----
// mma.sync.m16n8k16 fp16->fp32 (plain sm_103-legal path; tcgen05 needs 'a' target).
// Block: 128 rows x 64 cols, K=128; 8 warps, warp = 16 rows x 64 cols.
__global__ void __launch_bounds__(256, 2)
k_gemm_mma(const uint2* __restrict__ Aah, const uint2* __restrict__ Axh,
           const float* __restrict__ Wr,  const float* __restrict__ Ws,
           const float* __restrict__ br,  __half* __restrict__ outh) {
    extern __shared__ char smem[];
    __half* sA = (__half*)smem;                       // [128][136]
    __half* sB = (__half*)(smem + SA_BYTES);          // [64][136]  B[n][k]
    float*  sBias = (float*)(smem + SA_BYTES + SB_BYTES);
    int t = threadIdx.x;
    int n0g = blockIdx.x * 128;

    // ---- stage A: row r, halves kh*64..: kh=0 -> agg (k 0-63), kh=1 -> x (k 64-127)
    {
        int r = t >> 1, kh = t & 1;
        int n = n0g + r;
        const uint4* p = (const uint4*)((kh ? Axh : Aah) + (size_t)n * 16);
        uint4 z = make_uint4(0, 0, 0, 0);
        __half* dst = sA + r * 136 + kh * 64;
#pragma unroll
        for (int j = 0; j < 8; j++) {
            uint4 v = (n < NN) ? p[j] : z;
            *(uint4*)(dst + j * 8) = v;
        }
    }
    // ---- stage B: sB[n][k] = (k<64 ? Wr[k][n] : Ws[k-64][n]), fp16
    if (t < 128) {
        int n = t >> 1, kh = t & 1;
        const float* W = kh ? Ws : Wr;
        __half* dst = sB + n * 136 + kh * 64;
#pragma unroll
        for (int k2 = 0; k2 < 32; k2++) {
            float f0 = W[(2 * k2) * 64 + n];
            float f1 = W[(2 * k2 + 1) * 64 + n];
            *(__half2*)(dst + 2 * k2) = __floats2half2_rn(f0, f1);
        }
    }
    if (t < 64) sBias[t] = br[t];
    __syncthreads();

    int w = t >> 5, l = t & 31;
    // ldmatrix lane addressing (8x8 b16 matrices):
    // A x4: m0 rows w16+0-7 k0 | m1 rows +8 k0 | m2 rows 0-7 k8 | m3 rows +8 k8
    int arow  = 16 * w + (l & 7) + ((l >> 3) & 1) * 8;
    int acolh = ((l >> 4) & 1) * 8;
    uint32_t aaddr = s2u(sA) + (uint32_t)(arow * 136 + acolh) * 2;
    // B x4 (group g = n rows 16g..16g+15): m0 n-low k0 | m1 n-low k8 | m2 n-high k0 | m3 n-high k8
    int bln   = (l & 7) + ((l >> 4) & 1) * 8;
    int bcolh = ((l >> 3) & 1) * 8;
    uint32_t baddr = s2u(sB) + (uint32_t)(bln * 136 + bcolh) * 2;

    float acc[8][4];
#pragma unroll
    for (int nt = 0; nt < 8; nt++)
#pragma unroll
        for (int i = 0; i < 4; i++) acc[nt][i] = 0.f;

#pragma unroll
    for (int kt = 0; kt < 8; kt++) {
        uint32_t a0, a1, a2, a3;
        asm volatile("ldmatrix.sync.aligned.m8n8.x4.shared.b16 {%0,%1,%2,%3}, [%4];"
            : "=r"(a0), "=r"(a1), "=r"(a2), "=r"(a3) : "r"(aaddr + kt * 32));
#pragma unroll
        for (int g = 0; g < 4; g++) {
            uint32_t b0, b1, b2, b3;
            asm volatile("ldmatrix.sync.aligned.m8n8.x4.shared.b16 {%0,%1,%2,%3}, [%4];"
                : "=r"(b0), "=r"(b1), "=r"(b2), "=r"(b3)
                : "r"(baddr + (uint32_t)g * (16 * 136 * 2) + kt * 32));
            asm volatile("mma.sync.aligned.m16n8k16.row.col.f32.f16.f16.f32 "
                "{%0,%1,%2,%3}, {%4,%5,%6,%7}, {%8,%9}, {%0,%1,%2,%3};"
                : "+f"(acc[2 * g][0]), "+f"(acc[2 * g][1]), "+f"(acc[2 * g][2]), "+f"(acc[2 * g][3])
                : "r"(a0), "r"(a1), "r"(a2), "r"(a3), "r"(b0), "r"(b1));
            asm volatile("mma.sync.aligned.m16n8k16.row.col.f32.f16.f16.f32 "
                "{%0,%1,%2,%3}, {%4,%5,%6,%7}, {%8,%9}, {%0,%1,%2,%3};"
                : "+f"(acc[2 * g + 1][0]), "+f"(acc[2 * g + 1][1]), "+f"(acc[2 * g + 1][2]), "+f"(acc[2 * g + 1][3])
                : "r"(a0), "r"(a1), "r"(a2), "r"(a3), "r"(b2), "r"(b3));
        }
    }

    // ---- epilogue: C frag = (row gid / gid+8, cols tig*2,+1) per n-tile
    int gid = l >> 2, tig = l & 3;
    int m0 = n0g + 16 * w + gid;
    int m1 = m0 + 8;
#pragma unroll
    for (int nt = 0; nt < 8; nt++) {
        int c = 8 * nt + tig * 2;
        float blo = sBias[c], bhi = sBias[c + 1];
        if (m0 < NN) {
            __half2 h = __floats2half2_rn(fmaxf(acc[nt][0] + blo, 0.f),
                                          fmaxf(acc[nt][1] + bhi, 0.f));
            *(__half2*)(outh + (size_t)m0 * 64 + c) = h;
        }
        if (m1 < NN) {
            __half2 h = __floats2half2_rn(fmaxf(acc[nt][2] + blo, 0.f),
                                          fmaxf(acc[nt][3] + bhi, 0.f));
            *(__half2*)(outh + (size_t)m1 * 64 + c) = h;
        }
    }
}

// ---------------- global add pool (fp16 in, fp32 out) ----------------
__device__ __forceinline__ int lower_bound_i(const int* __restrict__ a, int n, int v) {
    int lo = 0, hi = n;
    while (lo < hi) {
        int mid = (lo + hi) >> 1;
        if (a[mid] < v) lo = mid + 1; else hi = mid;
    }
    return lo;
}

__global__ void k_pool(const __half* __restrict__ h, const int* __restrict__ batch) {
    __shared__ float red[512];
    int g = blockIdx.x, t = threadIdx.x;
    int c = t & 63, q = t >> 6;
    int start = lower_bound_i(batch, NN, g);
    int end   = lower_bound_i(batch, NN, g + 1);
    float acc = 0.f;
    for (int n = start + q; n < end; n += 8)
        acc += __half2float(h[(size_t)n * 64 + c]);
    red[t] = acc;
    __syncthreads();
    if (q < 4) red[t] += red[t + 256];
    __syncthreads();
    if (q < 2) red[t] += red[t + 128];
    __syncthreads();
    if (q == 0)
        g_pool[g * 64 + c] = red[c] + red[c + 64];
}

// ---------------- FC head + log_softmax ----------------
__global__ void k_fc(const float* __restrict__ W1, const float* __restrict__ b1,
                     const float* __restrict__ W2, const float* __restrict__ b2,
                     float* __restrict__ out) {
    __shared__ float sg[64], sh[64], sl[3];
    int g = blockIdx.x, t = threadIdx.x;
    sg[t] = g_pool[g * 64 + t];
    __syncthreads();
    float a = b1[t];
#pragma unroll 8
    for (int k = 0; k < 64; k++) a += sg[k] * W1[k * 64 + t];
    sh[t] = fmaxf(a, 0.f);
    __syncthreads();
    if (t < 3) {
        float l = b2[t];
        for (int k = 0; k < 64; k++) l += sh[k] * W2[k * 3 + t];
        sl[t] = l;
    }
    __syncthreads();
    if (t < 3) {
        float m = fmaxf(sl[0], fmaxf(sl[1], sl[2]));
        float s = expf(sl[0] - m) + expf(sl[1] - m) + expf(sl[2] - m);
        out[g * 3 + t] = sl[t] - m - logf(s);
    }
}

// ------------------------------- launcher -------------------------------
extern "C" void kernel_launch(void* const* d_in, const int* in_sizes, int n_in,
                              void* d_out, int out_size) {
    const float* x     = (const float*)d_in[0];
    const int*   ei    = (const int*)d_in[1];
    const int*   src   = ei;
    const int*   dst   = ei + NE;
    const int*   batch = (const int*)d_in[2];
    const float* Wr1 = (const float*)d_in[3];
    const float* br1 = (const float*)d_in[4];
    const float* Ws1 = (const float*)d_in[5];
    const float* Wr2 = (const float*)d_in[6];
    const float* br2 = (const float*)d_in[7];
    const float* Ws2 = (const float*)d_in[8];
    const float* Wr3 = (const float*)d_in[9];
    const float* br3 = (const float*)d_in[10];
    const float* Ws3 = (const float*)d_in[11];
    const float* Wf1 = (const float*)d_in[12];
    const float* bf1 = (const float*)d_in[13];
    const float* Wf2 = (const float*)d_in[14];
    const float* bf2 = (const float*)d_in[15];
    float* out = (float*)d_out;

    cudaFuncSetAttribute(k_gemm_mma, cudaFuncAttributeMaxDynamicSharedMemorySize, GEMM_SMEM);

    uint2 *xh, *aggh, *hAh, *hBh;
    cudaGetSymbolAddress((void**)&xh,   g_xh);
    cudaGetSymbolAddress((void**)&aggh, g_aggh);
    cudaGetSymbolAddress((void**)&hAh,  g_hAh);
    cudaGetSymbolAddress((void**)&hBh,  g_hBh);

    // cvt also zeroes g_deg / g_scanpkt
    k_cvt<<<(NN * 16 + 255) / 256, 256>>>(x, xh);
    k_hist<<<(NE + 255) / 256, 256>>>(dst);
    k_scan<<<NCHUNK, SCAN_CHUNK>>>();
    k_scatter<<<(NE + 255) / 256, 256>>>(src, dst);

    const int AGG_GRID  = (NN + 15) / 16;
    const int GEMM_GRID = (NN + 127) / 128;

    // layer 1
    k_agg<<<AGG_GRID, 256>>>(xh);
    k_gemm_mma<<<GEMM_GRID, 256, GEMM_SMEM>>>(aggh, xh, Wr1, Ws1, br1, (__half*)hAh);
    // layer 2
    k_agg<<<AGG_GRID, 256>>>(hAh);
    k_gemm_mma<<<GEMM_GRID, 256, GEMM_SMEM>>>(aggh, hAh, Wr2, Ws2, br2, (__half*)hBh);
    // layer 3
    k_agg<<<AGG_GRID, 256>>>(hBh);
    k_gemm_mma<<<GEMM_GRID, 256, GEMM_SMEM>>>(aggh, hBh, Wr3, Ws3, br3, (__half*)hAh);

    // pool + head
    k_pool<<<NG, 512>>>((const __half*)hAh, batch);
    k_fc<<<NG, 64>>>(Wf1, bf1, Wf2, bf2, out);
}

// round 17
// speedup vs baseline: 1.8494x; 1.5534x over previous
#include <cuda_runtime.h>
#include <cuda_fp16.h>
#include <math.h>
#include <stdint.h>

#define NN 100000
#define NE 1200000
#define DH 64
#define NG 128
#define SCAN_CHUNK 1024
#define NCHUNK 98            // ceil(NN / SCAN_CHUNK)

// mma gemm smem: sA[128][136] fp16 + sB[64][136] fp16 + bias[64] f32
#define SA_BYTES (128 * 136 * 2)          // 34816
#define SB_BYTES (64 * 136 * 2)           // 17408
#define GEMM_SMEM (SA_BYTES + SB_BYTES + 256)   // 52480 -> 2 blocks/SM

__device__ __forceinline__ uint32_t s2u(const void* p) {
    uint32_t a;
    asm("{ .reg .u64 t; cvta.to.shared.u64 t, %1; cvt.u32.u64 %0, t; }" : "=r"(a) : "l"(p));
    return a;
}

// -------- scratch (static device allocations; no cudaMalloc anywhere) --------
// Invariant: g_deg and g_scanpkt are ZERO on entry to kernel_launch (zero-init
// on first call; k_scan / k_scatter re-zero them after use on every replay).
__device__ int                g_deg[NN];
__device__ unsigned long long g_scanpkt[NCHUNK];
__device__ int                g_rowptr[NN + 1];
__device__ int                g_erank[NE];              // edge rank within its dst bucket
__device__ int                g_esrc[NE];
__device__ __half             g_W16[3 * 64 * 128];      // per-layer B tile [64 n][128 k]
__device__ uint4              g_xh [(size_t)NN * 8];    // fp16 x      (64 halves/row)
__device__ uint4              g_aggh[(size_t)NN * 8];   // fp16 agg
__device__ uint4              g_hAh[(size_t)NN * 8];    // fp16 layer out A
__device__ uint4              g_hBh[(size_t)NN * 8];    // fp16 layer out B
__device__ float              g_pool[NG * DH];

// ---- k_cvt: x fp32->fp16, edge histogram + ranks, W fp32->fp16 B-layout ----
__global__ void k_cvt(const float* __restrict__ x, const int* __restrict__ dst,
                      const float* __restrict__ Wr1, const float* __restrict__ Ws1,
                      const float* __restrict__ Wr2, const float* __restrict__ Ws2,
                      const float* __restrict__ Wr3, const float* __restrict__ Ws3) {
    int i = blockIdx.x * blockDim.x + threadIdx.x;
    // x convert: one uint2 (4 floats) per thread, i < NN*16
    if (i < NN * 16) {
        float4 f = *(const float4*)(x + (size_t)i * 4);
        __half2 h0 = __floats2half2_rn(f.x, f.y);
        __half2 h1 = __floats2half2_rn(f.z, f.w);
        ((uint2*)g_xh)[i] = make_uint2(*(unsigned*)&h0, *(unsigned*)&h1);
    }
    // histogram + rank capture (deg is zero on entry by invariant)
    if (i < NE) {
        g_erank[i] = atomicAdd(&g_deg[dst[i]], 1);
    }
    // W prep: B[n][k] = (k<64 ? Wr[k][n] : Ws[k-64][n]) per layer
    if (i < 3 * 8192) {
        int layer = i >> 13, r = i & 8191;
        int n = r >> 7, k = r & 127;
        const float* Wr = layer == 0 ? Wr1 : (layer == 1 ? Wr2 : Wr3);
        const float* Ws = layer == 0 ? Ws1 : (layer == 1 ? Ws2 : Ws3);
        float v = (k < 64) ? Wr[k * 64 + n] : Ws[(k - 64) * 64 + n];
        g_W16[i] = __float2half_rn(v);
    }
}

// ---------------- exclusive scan of deg -> rowptr (decoupled lookback) ----------------
__global__ void k_scan() {
    __shared__ int s[SCAN_CHUNK];
    __shared__ int s_excl;
    int b = blockIdx.x, t = threadIdx.x;
    int idx = b * SCAN_CHUNK + t;
    int d = (idx < NN) ? g_deg[idx] : 0;
    s[t] = d;
    __syncthreads();
    for (int off = 1; off < SCAN_CHUNK; off <<= 1) {
        int v = (t >= off) ? s[t - off] : 0;
        __syncthreads();
        s[t] += v;
        __syncthreads();
    }
    int total = s[SCAN_CHUNK - 1];
    if (t == 0) {
        int excl = 0;
        if (b == 0) {
            atomicExch(&g_scanpkt[0], (2ull << 32) | (unsigned)total);
        } else {
            atomicExch(&g_scanpkt[b], (1ull << 32) | (unsigned)total);
            int run = 0;
            for (int p = b - 1; p >= 0; p--) {
                unsigned long long v;
                do { v = atomicAdd(&g_scanpkt[p], 0ull); } while ((v >> 32) == 0ull);
                run += (int)(v & 0xffffffffull);
                if ((v >> 32) == 2ull) break;
            }
            excl = run;
            atomicExch(&g_scanpkt[b], (2ull << 32) | (unsigned)(excl + total));
        }
        s_excl = excl;
        if (b == NCHUNK - 1) g_rowptr[NN] = excl + total;
    }
    __syncthreads();
    int excl = s_excl;
    if (idx < NN) {
        g_rowptr[idx] = s[t] - d + excl;
        g_deg[idx] = 0;                      // restore zero-invariant for next replay
    }
}

// ---------------- scatter (atomic-free: rowptr + precomputed rank) ----------------
__global__ void k_scatter(const int* __restrict__ src, const int* __restrict__ dst) {
    int e = blockIdx.x * blockDim.x + threadIdx.x;
    if (e < NCHUNK) g_scanpkt[e] = 0ull;     // restore zero-invariant for next replay
    if (e < NE) {
        int p = g_rowptr[dst[e]] + g_erank[e];
        g_esrc[p] = src[e];
    }
}

// ---------------- neighbor aggregation (fp16 gather, fp32 accumulate, fp16 out) ----
// 8 threads per node, one uint4 (8 halves, 16B) each; 4-wide index batching.
__device__ __forceinline__ void acc8(float* a, uint4 v) {
    __half2 h0 = *reinterpret_cast<__half2*>(&v.x);
    __half2 h1 = *reinterpret_cast<__half2*>(&v.y);
    __half2 h2 = *reinterpret_cast<__half2*>(&v.z);
    __half2 h3 = *reinterpret_cast<__half2*>(&v.w);
    float2 f0 = __half22float2(h0), f1 = __half22float2(h1);
    float2 f2 = __half22float2(h2), f3 = __half22float2(h3);
    a[0] += f0.x; a[1] += f0.y; a[2] += f1.x; a[3] += f1.y;
    a[4] += f2.x; a[5] += f2.y; a[6] += f3.x; a[7] += f3.y;
}

__global__ void k_agg(const uint4* __restrict__ in4) {
    int t = threadIdx.x;
    int n = blockIdx.x * 32 + (t >> 3);
    int c = t & 7;
    if (n >= NN) return;
    int rb = g_rowptr[n], re = g_rowptr[n + 1];
    float a0[8] = {0.f, 0.f, 0.f, 0.f, 0.f, 0.f, 0.f, 0.f};
    float a1[8] = {0.f, 0.f, 0.f, 0.f, 0.f, 0.f, 0.f, 0.f};
    int j = rb;
    for (; j + 4 <= re; j += 4) {
        int s0 = g_esrc[j],     s1 = g_esrc[j + 1];
        int s2 = g_esrc[j + 2], s3 = g_esrc[j + 3];
        uint4 v0 = in4[(size_t)s0 * 8 + c];
        uint4 v1 = in4[(size_t)s1 * 8 + c];
        uint4 v2 = in4[(size_t)s2 * 8 + c];
        uint4 v3 = in4[(size_t)s3 * 8 + c];
        acc8(a0, v0); acc8(a1, v1); acc8(a0, v2); acc8(a1, v3);
    }
    for (; j < re; j++) {
        uint4 v0 = in4[(size_t)g_esrc[j] * 8 + c];
        acc8(a0, v0);
    }
    __half2 o0 = __floats2half2_rn(a0[0] + a1[0], a0[1] + a1[1]);
    __half2 o1 = __floats2half2_rn(a0[2] + a1[2], a0[3] + a1[3]);
    __half2 o2 = __floats2half2_rn(a0[4] + a1[4], a0[5] + a1[5]);
    __half2 o3 = __floats2half2_rn(a0[6] + a1[6], a0[7] + a1[7]);
    g_aggh[(size_t)n * 8 + c] = make_uint4(*(unsigned*)&o0, *(unsigned*)&o1,
                                           *(unsigned*)&o2, *(unsigned*)&o3);
}

// ---------- tensor-core transform: out = relu([agg|x] @ [Wr;Ws] + br), fp16 out ----
// mma.sync.m16n8k16 fp16->fp32. Block: 128 rows x 64 cols, K=128; 8 warps.
__global__ void __launch_bounds__(256, 2)
k_gemm_mma(const uint4* __restrict__ Aah, const uint4* __restrict__ Axh,
           const uint4* __restrict__ W16, const float* __restrict__ br,
           __half* __restrict__ outh) {
    extern __shared__ char smem[];
    __half* sA = (__half*)smem;                       // [128][136]
    __half* sB = (__half*)(smem + SA_BYTES);          // [64][136]  B[n][k]
    float*  sBias = (float*)(smem + SA_BYTES + SB_BYTES);
    int t = threadIdx.x;
    int n0g = blockIdx.x * 128;

    // ---- stage A: row r, kh=0 -> agg (k 0-63), kh=1 -> x (k 64-127)
    {
        int r = t >> 1, kh = t & 1;
        int n = n0g + r;
        const uint4* p = (kh ? Axh : Aah) + (size_t)n * 8;
        uint4 z = make_uint4(0, 0, 0, 0);
        __half* dstp = sA + r * 136 + kh * 64;
#pragma unroll
        for (int j = 0; j < 8; j++) {
            uint4 v = (n < NN) ? p[j] : z;
            *(uint4*)(dstp + j * 8) = v;
        }
    }
    // ---- stage B: coalesced uint4 copy of pre-converted W16
    //      g_W16 row-major [64 n][128 k] = 16 uint4 per row, 1024 uint4 total
    for (int idx = t; idx < 1024; idx += 256) {
        int n = idx >> 4, j = idx & 15;
        *(uint4*)(sB + n * 136 + j * 8) = W16[idx];
    }
    if (t < 64) sBias[t] = br[t];
    __syncthreads();

    int w = t >> 5, l = t & 31;
    int arow  = 16 * w + (l & 7) + ((l >> 3) & 1) * 8;
    int acolh = ((l >> 4) & 1) * 8;
    uint32_t aaddr = s2u(sA) + (uint32_t)(arow * 136 + acolh) * 2;
    int bln   = (l & 7) + ((l >> 4) & 1) * 8;
    int bcolh = ((l >> 3) & 1) * 8;
    uint32_t baddr = s2u(sB) + (uint32_t)(bln * 136 + bcolh) * 2;

    float acc[8][4];
#pragma unroll
    for (int nt = 0; nt < 8; nt++)
#pragma unroll
        for (int i = 0; i < 4; i++) acc[nt][i] = 0.f;

#pragma unroll
    for (int kt = 0; kt < 8; kt++) {
        uint32_t a0, a1, a2, a3;
        asm volatile("ldmatrix.sync.aligned.m8n8.x4.shared.b16 {%0,%1,%2,%3}, [%4];"
            : "=r"(a0), "=r"(a1), "=r"(a2), "=r"(a3) : "r"(aaddr + kt * 32));
#pragma unroll
        for (int g = 0; g < 4; g++) {
            uint32_t b0, b1, b2, b3;
            asm volatile("ldmatrix.sync.aligned.m8n8.x4.shared.b16 {%0,%1,%2,%3}, [%4];"
                : "=r"(b0), "=r"(b1), "=r"(b2), "=r"(b3)
                : "r"(baddr + (uint32_t)g * (16 * 136 * 2) + kt * 32));
            asm volatile("mma.sync.aligned.m16n8k16.row.col.f32.f16.f16.f32 "
                "{%0,%1,%2,%3}, {%4,%5,%6,%7}, {%8,%9}, {%0,%1,%2,%3};"
                : "+f"(acc[2 * g][0]), "+f"(acc[2 * g][1]), "+f"(acc[2 * g][2]), "+f"(acc[2 * g][3])
                : "r"(a0), "r"(a1), "r"(a2), "r"(a3), "r"(b0), "r"(b1));
            asm volatile("mma.sync.aligned.m16n8k16.row.col.f32.f16.f16.f32 "
                "{%0,%1,%2,%3}, {%4,%5,%6,%7}, {%8,%9}, {%0,%1,%2,%3};"
                : "+f"(acc[2 * g + 1][0]), "+f"(acc[2 * g + 1][1]), "+f"(acc[2 * g + 1][2]), "+f"(acc[2 * g + 1][3])
                : "r"(a0), "r"(a1), "r"(a2), "r"(a3), "r"(b2), "r"(b3));
        }
    }

    int gid = l >> 2, tig = l & 3;
    int m0 = n0g + 16 * w + gid;
    int m1 = m0 + 8;
#pragma unroll
    for (int nt = 0; nt < 8; nt++) {
        int c = 8 * nt + tig * 2;
        float blo = sBias[c], bhi = sBias[c + 1];
        if (m0 < NN) {
            __half2 h = __floats2half2_rn(fmaxf(acc[nt][0] + blo, 0.f),
                                          fmaxf(acc[nt][1] + bhi, 0.f));
            *(__half2*)(outh + (size_t)m0 * 64 + c) = h;
        }
        if (m1 < NN) {
            __half2 h = __floats2half2_rn(fmaxf(acc[nt][2] + blo, 0.f),
                                          fmaxf(acc[nt][3] + bhi, 0.f));
            *(__half2*)(outh + (size_t)m1 * 64 + c) = h;
        }
    }
}

// ---------------- global add pool (fp16 in, fp32 out) ----------------
__device__ __forceinline__ int lower_bound_i(const int* __restrict__ a, int n, int v) {
    int lo = 0, hi = n;
    while (lo < hi) {
        int mid = (lo + hi) >> 1;
        if (a[mid] < v) lo = mid + 1; else hi = mid;
    }
    return lo;
}

__global__ void k_pool(const __half* __restrict__ h, const int* __restrict__ batch) {
    __shared__ float red[512];
    int g = blockIdx.x, t = threadIdx.x;
    int c = t & 63, q = t >> 6;
    int start = lower_bound_i(batch, NN, g);
    int end   = lower_bound_i(batch, NN, g + 1);
    float acc = 0.f;
    for (int n = start + q; n < end; n += 8)
        acc += __half2float(h[(size_t)n * 64 + c]);
    red[t] = acc;
    __syncthreads();
    if (q < 4) red[t] += red[t + 256];
    __syncthreads();
    if (q < 2) red[t] += red[t + 128];
    __syncthreads();
    if (q == 0)
        g_pool[g * 64 + c] = red[c] + red[c + 64];
}

// ---------------- FC head + log_softmax ----------------
__global__ void k_fc(const float* __restrict__ W1, const float* __restrict__ b1,
                     const float* __restrict__ W2, const float* __restrict__ b2,
                     float* __restrict__ out) {
    __shared__ float sg[64], sh[64], sl[3];
    int g = blockIdx.x, t = threadIdx.x;
    sg[t] = g_pool[g * 64 + t];
    __syncthreads();
    float a = b1[t];
#pragma unroll 8
    for (int k = 0; k < 64; k++) a += sg[k] * W1[k * 64 + t];
    sh[t] = fmaxf(a, 0.f);
    __syncthreads();
    if (t < 3) {
        float l = b2[t];
        for (int k = 0; k < 64; k++) l += sh[k] * W2[k * 3 + t];
        sl[t] = l;
    }
    __syncthreads();
    if (t < 3) {
        float m = fmaxf(sl[0], fmaxf(sl[1], sl[2]));
        float s = expf(sl[0] - m) + expf(sl[1] - m) + expf(sl[2] - m);
        out[g * 3 + t] = sl[t] - m - logf(s);
    }
}

// ------------------------------- launcher -------------------------------
extern "C" void kernel_launch(void* const* d_in, const int* in_sizes, int n_in,
                              void* d_out, int out_size) {
    const float* x     = (const float*)d_in[0];
    const int*   ei    = (const int*)d_in[1];
    const int*   src   = ei;
    const int*   dst   = ei + NE;
    const int*   batch = (const int*)d_in[2];
    const float* Wr1 = (const float*)d_in[3];
    const float* br1 = (const float*)d_in[4];
    const float* Ws1 = (const float*)d_in[5];
    const float* Wr2 = (const float*)d_in[6];
    const float* br2 = (const float*)d_in[7];
    const float* Ws2 = (const float*)d_in[8];
    const float* Wr3 = (const float*)d_in[9];
    const float* br3 = (const float*)d_in[10];
    const float* Ws3 = (const float*)d_in[11];
    const float* Wf1 = (const float*)d_in[12];
    const float* bf1 = (const float*)d_in[13];
    const float* Wf2 = (const float*)d_in[14];
    const float* bf2 = (const float*)d_in[15];
    float* out = (float*)d_out;

    cudaFuncSetAttribute(k_gemm_mma, cudaFuncAttributeMaxDynamicSharedMemorySize, GEMM_SMEM);

    uint4 *xh, *aggh, *hAh, *hBh;
    __half* w16;
    cudaGetSymbolAddress((void**)&xh,   g_xh);
    cudaGetSymbolAddress((void**)&aggh, g_aggh);
    cudaGetSymbolAddress((void**)&hAh,  g_hAh);
    cudaGetSymbolAddress((void**)&hBh,  g_hBh);
    cudaGetSymbolAddress((void**)&w16,  g_W16);

    // 1: convert x + histogram/ranks + W prep (deg/scanpkt zero by invariant)
    k_cvt<<<(NN * 16 + 255) / 256, 256>>>(x, dst, Wr1, Ws1, Wr2, Ws2, Wr3, Ws3);
    // 2: rowptr scan (re-zeroes deg)
    k_scan<<<NCHUNK, SCAN_CHUNK>>>();
    // 3: atomic-free scatter (re-zeroes scanpkt)
    k_scatter<<<(NE + 255) / 256, 256>>>(src, dst);

    const int AGG_GRID  = (NN + 31) / 32;
    const int GEMM_GRID = (NN + 127) / 128;

    // layer 1  (k_agg is launch #4 -> ncu profile slot)
    k_agg<<<AGG_GRID, 256>>>(xh);
    k_gemm_mma<<<GEMM_GRID, 256, GEMM_SMEM>>>(aggh, xh, (const uint4*)w16, br1, (__half*)hAh);
    // layer 2
    k_agg<<<AGG_GRID, 256>>>(hAh);
    k_gemm_mma<<<GEMM_GRID, 256, GEMM_SMEM>>>(aggh, hAh, (const uint4*)(w16 + 8192), br2, (__half*)hBh);
    // layer 3
    k_agg<<<AGG_GRID, 256>>>(hBh);
    k_gemm_mma<<<GEMM_GRID, 256, GEMM_SMEM>>>(aggh, hBh, (const uint4*)(w16 + 16384), br3, (__half*)hAh);

    // pool + head
    k_pool<<<NG, 512>>>((const __half*)hAh, batch);
    k_fc<<<NG, 64>>>(Wf1, bf1, Wf2, bf2, out);
}